// round 2
// baseline (speedup 1.0000x reference)
#include <cuda_runtime.h>
#include <math.h>

// Problem constants (fixed shapes per reference)
#define NVOX 40000
#define PPTS 32
#define CIN  10
#define GCH  64
#define HID  128
#define H3   384
#define MB   64                 // voxels per block
#define NTHREADS 256
#define NBLOCKS (NVOX / MB)     // 625 (exact)
#define KT   16                 // K-tile rows staged per iteration

// Transposed weight scratch: WT[k][gate_row], rows:
//   [0,64)   Wih_l0^T   (K=64)
//   [64,192) Whh_l0^T   (K=128)
//   [192,320) Wih_l1^T  (K=128)
//   [320,448) Whh_l1^T  (K=128)
#define WT_ROWS 448
__device__ float g_WT[WT_ROWS * H3];

__global__ void prep_weights(const float* __restrict__ wih0, const float* __restrict__ whh0,
                             const float* __restrict__ wih1, const float* __restrict__ whh1) {
    int idx = blockIdx.x * blockDim.x + threadIdx.x;
    const int total = WT_ROWS * H3;
    for (; idx < total; idx += gridDim.x * blockDim.x) {
        int row = idx / H3;
        int j   = idx - row * H3;   // gate row 0..383
        float v;
        if (row < 64)       v = wih0[j * 64  + row];
        else if (row < 192) v = whh0[j * 128 + (row - 64)];
        else if (row < 320) v = wih1[j * 128 + (row - 192)];
        else                v = whh1[j * 128 + (row - 320)];
        g_WT[idx] = v;
    }
}

__device__ __forceinline__ float sigmoidf_(float x) { return 1.0f / (1.0f + expf(-x)); }

// Accumulate A[v][k] * WT[rowBase+k][gcol] into per-thread accumulators.
// Thread (tx,ty): voxels v = ty*8+i (i<8), gate cols gc = tx+32*m:
//   aR <- cols [0,128), aZ <- cols [128,256), aN <- cols [256,384)
// Bank behavior: a-loads are warp-broadcast; b-loads hit bank==tx (conflict-free).
template<int SEGK>
__device__ __forceinline__ void gemm_seg(
    int rowBase, const float* __restrict__ sA, int lda,
    float* sW, int tid, int tx, int ty,
    float (&aR)[8][4], float (&aZ)[8][4], float (&aN)[8][4])
{
    const int NT = SEGK / KT;
    for (int tile = 0; tile < NT; ++tile) {
        __syncthreads();                       // prior users of sW done
        const float* src = g_WT + (size_t)(rowBase + tile * KT) * H3;
        for (int idx = tid; idx < KT * H3; idx += NTHREADS)
            sW[idx] = src[idx];                // coalesced L2 read, conflict-free smem write
        __syncthreads();
        const int k0 = tile * KT;
        #pragma unroll 4
        for (int kk = 0; kk < KT; ++kk) {
            float a[8];
            #pragma unroll
            for (int i = 0; i < 8; ++i)
                a[i] = sA[(ty * 8 + i) * lda + k0 + kk];
            const float* wrow = sW + kk * H3 + tx;
            #pragma unroll
            for (int m = 0; m < 4; ++m) {
                float br = wrow[32 * m];
                float bz = wrow[128 + 32 * m];
                float bn = wrow[256 + 32 * m];
                #pragma unroll
                for (int i = 0; i < 8; ++i) {
                    aR[i][m] = fmaf(a[i], br, aR[i][m]);
                    aZ[i][m] = fmaf(a[i], bz, aZ[i][m]);
                    aN[i][m] = fmaf(a[i], bn, aN[i][m]);
                }
            }
        }
    }
}

__global__ void __launch_bounds__(NTHREADS)
pfn_kernel(const float* __restrict__ inputs, const int* __restrict__ vnp,
           const float* __restrict__ conv_w,
           const float* __restrict__ bn_gamma, const float* __restrict__ bn_beta,
           const float* __restrict__ bn_mean,  const float* __restrict__ bn_var,
           const float* __restrict__ b_ih0, const float* __restrict__ b_hh0,
           const float* __restrict__ b_ih1, const float* __restrict__ b_hh1,
           float* __restrict__ out)
{
    extern __shared__ float sm[];
    float* sW   = sm;                    // KT*384 = 6144
    float* sX   = sW  + KT * H3;         // 64*64
    float* sH1  = sX  + MB * GCH;        // 64*128
    float* sH2  = sH1 + MB * HID;        // 64*128
    float* sMax = sH2 + MB * HID;        // 64*64
    float* sIn  = sMax + MB * GCH;       // 64*10
    float* sCw  = sIn  + MB * CIN;       // 640 folded conv weights
    float* sCb  = sCw  + GCH * CIN;      // 64  folded conv bias
    float* sB0i = sCb  + GCH;            // 384
    float* sB0h = sB0i + H3;
    float* sB1i = sB0h + H3;
    float* sB1h = sB1i + H3;
    int*   sLen = (int*)(sB1h + H3);     // 64

    const int tid = threadIdx.x;
    const int tx = tid & 31, ty = tid >> 5;
    const int base = blockIdx.x * MB;

    // ---- one-time block setup ----
    for (int idx = tid; idx < MB * HID; idx += NTHREADS) { sH1[idx] = 0.f; sH2[idx] = 0.f; }
    for (int idx = tid; idx < MB * GCH; idx += NTHREADS) sMax[idx] = 0.f;  // relu>=0, so 0 init == reference max
    for (int idx = tid; idx < GCH * CIN; idx += NTHREADS) {
        int g = idx / CIN;
        float sc = bn_gamma[g] * rsqrtf(bn_var[g] + 1e-5f);
        sCw[idx] = conv_w[idx] * sc;
    }
    for (int idx = tid; idx < GCH; idx += NTHREADS) {
        float sc = bn_gamma[idx] * rsqrtf(bn_var[idx] + 1e-5f);
        sCb[idx] = bn_beta[idx] - bn_mean[idx] * sc;
    }
    for (int idx = tid; idx < H3; idx += NTHREADS) {
        sB0i[idx] = b_ih0[idx]; sB0h[idx] = b_hh0[idx];
        sB1i[idx] = b_ih1[idx]; sB1h[idx] = b_hh1[idx];
    }
    for (int idx = tid; idx < MB; idx += NTHREADS) sLen[idx] = vnp[base + idx];
    __syncthreads();

    float aR[8][4], aZ[8][4], aXN[8][4], aHN[8][4];

    for (int t = 0; t < PPTS; ++t) {
        // ---- load this step's point features ----
        for (int idx = tid; idx < MB * CIN; idx += NTHREADS) {
            int v = idx / CIN, c = idx - v * CIN;
            sIn[idx] = inputs[((size_t)(base + v) * PPTS + t) * CIN + c];
        }
        __syncthreads();
        // ---- conv1d(k=1) + BN + ReLU, running max ----
        for (int idx = tid; idx < MB * GCH; idx += NTHREADS) {
            int v = idx >> 6, g = idx & 63;
            float s = sCb[g];
            const float* pin = sIn + v * CIN;
            const float* pw  = sCw + g * CIN;
            #pragma unroll
            for (int c = 0; c < CIN; ++c) s = fmaf(pin[c], pw[c], s);
            s = fmaxf(s, 0.f);
            sX[idx] = s;
            sMax[idx] = fmaxf(sMax[idx], s);   // same thread owns (v,g) every t: no race
        }
        // (gemm_seg starts with __syncthreads: sX visible before use)

        // ======== GRU layer 0 ========
        #pragma unroll
        for (int m = 0; m < 4; ++m) {
            int gc = tx + 32 * m;
            float br  = sB0i[gc]       + sB0h[gc];
            float bz  = sB0i[128 + gc] + sB0h[128 + gc];
            float bxn = sB0i[256 + gc];
            float bhn = sB0h[256 + gc];
            #pragma unroll
            for (int i = 0; i < 8; ++i) { aR[i][m] = br; aZ[i][m] = bz; aXN[i][m] = bxn; aHN[i][m] = bhn; }
        }
        gemm_seg<GCH>(0,  sX,  GCH, sW, tid, tx, ty, aR, aZ, aXN);   // x-projection
        gemm_seg<HID>(64, sH1, HID, sW, tid, tx, ty, aR, aZ, aHN);   // h-projection
        #pragma unroll
        for (int i = 0; i < 8; ++i) {
            int v = ty * 8 + i;
            #pragma unroll
            for (int m = 0; m < 4; ++m) {
                int hc = tx + 32 * m;
                float hp = sH1[v * HID + hc];
                float r = sigmoidf_(aR[i][m]);
                float z = sigmoidf_(aZ[i][m]);
                float n = tanhf(fmaf(r, aHN[i][m], aXN[i][m]));
                aR[i][m] = (1.f - z) * n + z * hp;   // h1_new held in regs
            }
        }
        __syncthreads();                              // all reads of old sH1 done
        #pragma unroll
        for (int i = 0; i < 8; ++i) {
            int v = ty * 8 + i;
            #pragma unroll
            for (int m = 0; m < 4; ++m) sH1[v * HID + tx + 32 * m] = aR[i][m];
        }

        // ======== GRU layer 1 ========
        #pragma unroll
        for (int m = 0; m < 4; ++m) {
            int gc = tx + 32 * m;
            float br  = sB1i[gc]       + sB1h[gc];
            float bz  = sB1i[128 + gc] + sB1h[128 + gc];
            float bxn = sB1i[256 + gc];
            float bhn = sB1h[256 + gc];
            #pragma unroll
            for (int i = 0; i < 8; ++i) { aR[i][m] = br; aZ[i][m] = bz; aXN[i][m] = bxn; aHN[i][m] = bhn; }
        }
        gemm_seg<HID>(192, sH1, HID, sW, tid, tx, ty, aR, aZ, aXN);  // x = h1_new
        gemm_seg<HID>(320, sH2, HID, sW, tid, tx, ty, aR, aZ, aHN);  // h = h2
        #pragma unroll
        for (int i = 0; i < 8; ++i) {
            int v = ty * 8 + i;
            #pragma unroll
            for (int m = 0; m < 4; ++m) {
                int hc = tx + 32 * m;
                float hp = sH2[v * HID + hc];
                float r = sigmoidf_(aR[i][m]);
                float z = sigmoidf_(aZ[i][m]);
                float n = tanhf(fmaf(r, aHN[i][m], aXN[i][m]));
                aR[i][m] = (1.f - z) * n + z * hp;   // h2_new
            }
        }
        __syncthreads();                              // all reads of old sH2 done
        #pragma unroll
        for (int i = 0; i < 8; ++i) {
            int v = ty * 8 + i;
            int len = sLen[v];
            #pragma unroll
            for (int m = 0; m < 4; ++m) {
                int hc = tx + 32 * m;
                float h2n = aR[i][m];
                sH2[v * HID + hc] = h2n;
                if (t == len - 1)
                    out[(size_t)(base + v) * (GCH + HID) + GCH + hc] = h2n;  // gather at len-1
            }
        }
    }

    __syncthreads();
    for (int idx = tid; idx < MB * GCH; idx += NTHREADS) {
        int v = idx >> 6, g = idx & 63;
        out[(size_t)(base + v) * (GCH + HID) + g] = sMax[idx];
    }
}

extern "C" void kernel_launch(void* const* d_in, const int* in_sizes, int n_in,
                              void* d_out, int out_size) {
    const float* inputs = (const float*)d_in[0];
    const int*   vnp    = (const int*)  d_in[1];
    // d_in[2] = mask (unused by reference)
    const float* conv_w = (const float*)d_in[3];
    const float* bn_g   = (const float*)d_in[4];
    const float* bn_b   = (const float*)d_in[5];
    const float* bn_m   = (const float*)d_in[6];
    const float* bn_v   = (const float*)d_in[7];
    const float* wih0   = (const float*)d_in[8];
    const float* whh0   = (const float*)d_in[9];
    const float* bih0   = (const float*)d_in[10];
    const float* bhh0   = (const float*)d_in[11];
    const float* wih1   = (const float*)d_in[12];
    const float* whh1   = (const float*)d_in[13];
    const float* bih1   = (const float*)d_in[14];
    const float* bhh1   = (const float*)d_in[15];
    float* out = (float*)d_out;

    const int smem_bytes = (KT * H3 + MB * GCH + 2 * MB * HID + MB * GCH + MB * CIN
                            + GCH * CIN + GCH + 4 * H3 + MB) * (int)sizeof(float);
    cudaFuncSetAttribute(pfn_kernel, cudaFuncAttributeMaxDynamicSharedMemorySize, smem_bytes);

    prep_weights<<<336, 512>>>(wih0, whh0, wih1, whh1);
    pfn_kernel<<<NBLOCKS, NTHREADS, smem_bytes>>>(inputs, vnp, conv_w, bn_g, bn_b, bn_m, bn_v,
                                                  bih0, bhh0, bih1, bhh1, out);
}

// round 3
// speedup vs baseline: 1.8489x; 1.8489x over previous
#include <cuda_runtime.h>
#include <math.h>

// Shapes (fixed)
#define NVOX 40000
#define PPTS 32
#define CIN  10
#define GCH  64
#define HID  128
#define H3   384
#define MB   64                 // voxels per block
#define NTHREADS 256
#define NBLOCKS (NVOX / MB)     // 625 exact
#define KT   32                 // K rows staged per weight tile
#define STR  320                // activation row stride: [x(64) | h1(128) | h2(128)]

// Transposed stacked weights: WT[k][gate_col], k rows:
// [0,64) Wih0^T, [64,192) Whh0^T, [192,320) Wih1^T, [320,448) Whh1^T
#define WT_ROWS 448
__device__ float g_WT[WT_ROWS * H3];
__device__ int   g_perm[NVOX];
__device__ int   g_hist[32];
__device__ int   g_off[33];

__global__ void prep_weights(const float* __restrict__ wih0, const float* __restrict__ whh0,
                             const float* __restrict__ wih1, const float* __restrict__ whh1) {
    int idx = blockIdx.x * blockDim.x + threadIdx.x;
    const int total = WT_ROWS * H3;
    for (; idx < total; idx += gridDim.x * blockDim.x) {
        int row = idx / H3;
        int j   = idx - row * H3;
        float v;
        if (row < 64)       v = wih0[j * 64  + row];
        else if (row < 192) v = whh0[j * 128 + (row - 64)];
        else if (row < 320) v = wih1[j * 128 + (row - 192)];
        else                v = whh1[j * 128 + (row - 320)];
        g_WT[idx] = v;
    }
}

// ---- deterministic stable counting sort of voxels by length ----
__global__ void zero_hist() { if (threadIdx.x < 32) g_hist[threadIdx.x] = 0; }

__global__ void hist_kernel(const int* __restrict__ vnp) {
    int i = blockIdx.x * blockDim.x + threadIdx.x;
    for (; i < NVOX; i += gridDim.x * blockDim.x)
        atomicAdd(&g_hist[vnp[i] - 1], 1);
}

__global__ void scan_kernel() {
    if (threadIdx.x == 0) {
        int acc = 0;
        g_off[0] = 0;
        for (int b = 0; b < 32; ++b) { acc += g_hist[b]; g_off[b + 1] = acc; }
    }
}

// One block per length bin; stable order within bin (deterministic).
__global__ void binorder_kernel(const int* __restrict__ vnp) {
    __shared__ int s_base;
    __shared__ int warp_sums[8];
    const int tid = threadIdx.x;
    const int mylen = blockIdx.x + 1;
    if (tid == 0) s_base = g_off[blockIdx.x];
    __syncthreads();
    for (int start = 0; start < NVOX; start += 256) {
        int i = start + tid;
        int flag = (i < NVOX && vnp[i] == mylen);
        unsigned bal = __ballot_sync(0xffffffffu, flag);
        int wid = tid >> 5, lane = tid & 31;
        int wpre = __popc(bal & ((1u << lane) - 1u));
        if (lane == 0) warp_sums[wid] = __popc(bal);
        __syncthreads();
        int wbase = 0;
        for (int w = 0; w < wid; ++w) wbase += warp_sums[w];
        if (flag) g_perm[s_base + wbase + wpre] = i;
        __syncthreads();
        if (tid == 0) {
            int tot = 0;
            for (int w = 0; w < 8; ++w) tot += warp_sums[w];
            s_base += tot;
        }
        __syncthreads();
    }
}

__device__ __forceinline__ float sigmoidf_(float x) { return 1.0f / (1.0f + expf(-x)); }

// A[v][k] * WT[rowBase+k][col] -> accumulators.
// Thread (tx,ty): voxels v=ty*8+i, per-gate cols 4*tx..4*tx+3.
// w loads: 3x LDS.128 conflict-free; a loads: broadcast LDS.128 per voxel per 4k.
template<int SEGK>
__device__ __forceinline__ void gemm_seg(
    int rowBase, const float* sA0, float* sW, int tid, int tx, int ty,
    float (&aR)[8][4], float (&aZ)[8][4], float (&aN)[8][4])
{
    const int NT = SEGK / KT;
    #pragma unroll 1
    for (int tile = 0; tile < NT; ++tile) {
        __syncthreads();                       // previous users of sW done
        const float4* src = (const float4*)(g_WT + (size_t)(rowBase + tile * KT) * H3);
        float4* dst = (float4*)sW;
        #pragma unroll 1
        for (int idx = tid; idx < KT * H3 / 4; idx += NTHREADS)
            dst[idx] = src[idx];
        __syncthreads();
        const int k0 = tile * KT;
        #pragma unroll 1
        for (int kk4 = 0; kk4 < KT / 4; ++kk4) {
            float4 a4[8];
            #pragma unroll
            for (int i = 0; i < 8; ++i)
                a4[i] = *(const float4*)(sA0 + (ty * 8 + i) * STR + k0 + kk4 * 4);
            #pragma unroll
            for (int j = 0; j < 4; ++j) {
                const float* wrow = sW + (kk4 * 4 + j) * H3 + 4 * tx;
                float4 wr = *(const float4*)(wrow);
                float4 wz = *(const float4*)(wrow + HID);
                float4 wn = *(const float4*)(wrow + 2 * HID);
                #pragma unroll
                for (int i = 0; i < 8; ++i) {
                    float a = (j == 0) ? a4[i].x : (j == 1) ? a4[i].y
                            : (j == 2) ? a4[i].z : a4[i].w;
                    aR[i][0] = fmaf(a, wr.x, aR[i][0]);
                    aR[i][1] = fmaf(a, wr.y, aR[i][1]);
                    aR[i][2] = fmaf(a, wr.z, aR[i][2]);
                    aR[i][3] = fmaf(a, wr.w, aR[i][3]);
                    aZ[i][0] = fmaf(a, wz.x, aZ[i][0]);
                    aZ[i][1] = fmaf(a, wz.y, aZ[i][1]);
                    aZ[i][2] = fmaf(a, wz.z, aZ[i][2]);
                    aZ[i][3] = fmaf(a, wz.w, aZ[i][3]);
                    aN[i][0] = fmaf(a, wn.x, aN[i][0]);
                    aN[i][1] = fmaf(a, wn.y, aN[i][1]);
                    aN[i][2] = fmaf(a, wn.z, aN[i][2]);
                    aN[i][3] = fmaf(a, wn.w, aN[i][3]);
                }
            }
        }
    }
}

__global__ void __launch_bounds__(NTHREADS)
pfn_kernel(const float* __restrict__ inputs, const int* __restrict__ vnp,
           const float* __restrict__ conv_w,
           const float* __restrict__ bn_gamma, const float* __restrict__ bn_beta,
           const float* __restrict__ bn_mean,  const float* __restrict__ bn_var,
           const float* __restrict__ b_ih0, const float* __restrict__ b_hh0,
           const float* __restrict__ b_ih1, const float* __restrict__ b_hh1,
           float* __restrict__ out)
{
    extern __shared__ float sm[];
    float* sW   = sm;                     // KT*384 = 12288
    float* sA   = sW  + KT * H3;          // 64*320 = 20480  rows [x|h1|h2]
    float* sMax = sA  + MB * STR;         // 64*64
    float* sIn  = sMax + MB * GCH;        // 64*10
    float* sCw  = sIn  + MB * CIN;        // 640
    float* sCb  = sCw  + GCH * CIN;       // 64
    float* sB0i = sCb  + GCH;             // 4x384
    float* sB0h = sB0i + H3;
    float* sB1i = sB0h + H3;
    float* sB1h = sB1i + H3;
    int*   sLen = (int*)(sB1h + H3);      // 64
    int*   sVox = sLen + MB;              // 64

    const int tid = threadIdx.x;
    const int tx = tid & 31, ty = tid >> 5;
    const int base = blockIdx.x * MB;

    // ---- one-time setup ----
    for (int idx = tid; idx < MB * STR; idx += NTHREADS) sA[idx] = 0.f;
    for (int idx = tid; idx < MB * GCH; idx += NTHREADS) sMax[idx] = 0.f;
    for (int idx = tid; idx < GCH * CIN; idx += NTHREADS) {
        int g = idx / CIN;
        float sc = bn_gamma[g] * rsqrtf(bn_var[g] + 1e-5f);
        sCw[idx] = conv_w[idx] * sc;
    }
    for (int idx = tid; idx < GCH; idx += NTHREADS) {
        float sc = bn_gamma[idx] * rsqrtf(bn_var[idx] + 1e-5f);
        sCb[idx] = bn_beta[idx] - bn_mean[idx] * sc;
    }
    for (int idx = tid; idx < H3; idx += NTHREADS) {
        sB0i[idx] = b_ih0[idx]; sB0h[idx] = b_hh0[idx];
        sB1i[idx] = b_ih1[idx]; sB1h[idx] = b_hh1[idx];
    }
    for (int idx = tid; idx < MB; idx += NTHREADS) {
        int vox = g_perm[base + idx];
        sVox[idx] = vox;
        sLen[idx] = vnp[vox];
    }
    __syncthreads();

    int tmax = 0;
    for (int v = 0; v < MB; ++v) tmax = max(tmax, sLen[v]);

    // ---- prepass: conv+BN+ReLU max over ALL 32 points ----
    for (int t = 0; t < PPTS; ++t) {
        for (int idx = tid; idx < MB * CIN; idx += NTHREADS) {
            int v = idx / CIN, c = idx - v * CIN;
            sIn[idx] = inputs[((size_t)sVox[v] * PPTS + t) * CIN + c];
        }
        __syncthreads();
        for (int idx = tid; idx < MB * GCH; idx += NTHREADS) {
            int v = idx >> 6, g = idx & 63;
            float s = sCb[g];
            const float* pin = sIn + v * CIN;
            const float* pw  = sCw + g * CIN;
            #pragma unroll
            for (int c = 0; c < CIN; ++c) s = fmaf(pin[c], pw[c], s);
            sMax[idx] = fmaxf(sMax[idx], fmaxf(s, 0.f));
        }
        __syncthreads();
    }

    float aR[8][4], aZ[8][4], aXN[8][4], aHN[8][4];

    // ---- GRU over t < block max length only ----
    for (int t = 0; t < tmax; ++t) {
        for (int idx = tid; idx < MB * CIN; idx += NTHREADS) {
            int v = idx / CIN, c = idx - v * CIN;
            sIn[idx] = inputs[((size_t)sVox[v] * PPTS + t) * CIN + c];
        }
        __syncthreads();
        for (int idx = tid; idx < MB * GCH; idx += NTHREADS) {
            int v = idx >> 6, g = idx & 63;
            float s = sCb[g];
            const float* pin = sIn + v * CIN;
            const float* pw  = sCw + g * CIN;
            #pragma unroll
            for (int c = 0; c < CIN; ++c) s = fmaf(pin[c], pw[c], s);
            sA[v * STR + g] = fmaxf(s, 0.f);     // x segment
        }
        // (gemm_seg begins with __syncthreads)

        // ======== layer 0 ========
        {
            float4 bi = *(const float4*)(sB0i + 4 * tx);
            float4 bh = *(const float4*)(sB0h + 4 * tx);
            float4 bzi = *(const float4*)(sB0i + HID + 4 * tx);
            float4 bzh = *(const float4*)(sB0h + HID + 4 * tx);
            float4 bni = *(const float4*)(sB0i + 2 * HID + 4 * tx);
            float4 bnh = *(const float4*)(sB0h + 2 * HID + 4 * tx);
            float br[4] = {bi.x + bh.x, bi.y + bh.y, bi.z + bh.z, bi.w + bh.w};
            float bz[4] = {bzi.x + bzh.x, bzi.y + bzh.y, bzi.z + bzh.z, bzi.w + bzh.w};
            float bxn[4] = {bni.x, bni.y, bni.z, bni.w};
            float bhn[4] = {bnh.x, bnh.y, bnh.z, bnh.w};
            #pragma unroll
            for (int i = 0; i < 8; ++i)
                #pragma unroll
                for (int j = 0; j < 4; ++j) {
                    aR[i][j] = br[j]; aZ[i][j] = bz[j];
                    aXN[i][j] = bxn[j]; aHN[i][j] = bhn[j];
                }
        }
        gemm_seg<GCH>(0,  sA + 0,  sW, tid, tx, ty, aR, aZ, aXN);  // x part
        gemm_seg<HID>(64, sA + 64, sW, tid, tx, ty, aR, aZ, aHN);  // h1 part
        #pragma unroll
        for (int i = 0; i < 8; ++i) {
            int v = ty * 8 + i;
            float4 hp = *(const float4*)(sA + v * STR + 64 + 4 * tx);
            #pragma unroll
            for (int j = 0; j < 4; ++j) {
                float h = (j == 0) ? hp.x : (j == 1) ? hp.y : (j == 2) ? hp.z : hp.w;
                float r = sigmoidf_(aR[i][j]);
                float z = sigmoidf_(aZ[i][j]);
                float n = tanhf(fmaf(r, aHN[i][j], aXN[i][j]));
                aR[i][j] = (1.f - z) * n + z * h;   // h1_new in regs
            }
        }
        __syncthreads();                            // all reads of old h1 done
        #pragma unroll
        for (int i = 0; i < 8; ++i) {
            int v = ty * 8 + i;
            float4 h4 = make_float4(aR[i][0], aR[i][1], aR[i][2], aR[i][3]);
            *(float4*)(sA + v * STR + 64 + 4 * tx) = h4;
        }

        // ======== layer 1 ========
        {
            float4 bi = *(const float4*)(sB1i + 4 * tx);
            float4 bh = *(const float4*)(sB1h + 4 * tx);
            float4 bzi = *(const float4*)(sB1i + HID + 4 * tx);
            float4 bzh = *(const float4*)(sB1h + HID + 4 * tx);
            float4 bni = *(const float4*)(sB1i + 2 * HID + 4 * tx);
            float4 bnh = *(const float4*)(sB1h + 2 * HID + 4 * tx);
            float br[4] = {bi.x + bh.x, bi.y + bh.y, bi.z + bh.z, bi.w + bh.w};
            float bz[4] = {bzi.x + bzh.x, bzi.y + bzh.y, bzi.z + bzh.z, bzi.w + bzh.w};
            float bxn[4] = {bni.x, bni.y, bni.z, bni.w};
            float bhn[4] = {bnh.x, bnh.y, bnh.z, bnh.w};
            #pragma unroll
            for (int i = 0; i < 8; ++i)
                #pragma unroll
                for (int j = 0; j < 4; ++j) {
                    aR[i][j] = br[j]; aZ[i][j] = bz[j];
                    aXN[i][j] = bxn[j]; aHN[i][j] = bhn[j];
                }
        }
        gemm_seg<HID>(192, sA + 64,  sW, tid, tx, ty, aR, aZ, aXN); // x = h1_new
        gemm_seg<HID>(320, sA + 192, sW, tid, tx, ty, aR, aZ, aHN); // h2 part
        #pragma unroll
        for (int i = 0; i < 8; ++i) {
            int v = ty * 8 + i;
            float4 hp = *(const float4*)(sA + v * STR + 192 + 4 * tx);
            #pragma unroll
            for (int j = 0; j < 4; ++j) {
                float h = (j == 0) ? hp.x : (j == 1) ? hp.y : (j == 2) ? hp.z : hp.w;
                float r = sigmoidf_(aR[i][j]);
                float z = sigmoidf_(aZ[i][j]);
                float n = tanhf(fmaf(r, aHN[i][j], aXN[i][j]));
                aR[i][j] = (1.f - z) * n + z * h;   // h2_new
            }
        }
        __syncthreads();                            // all reads of old h2 done
        #pragma unroll
        for (int i = 0; i < 8; ++i) {
            int v = ty * 8 + i;
            float4 h4 = make_float4(aR[i][0], aR[i][1], aR[i][2], aR[i][3]);
            *(float4*)(sA + v * STR + 192 + 4 * tx) = h4;
            if (t == sLen[v] - 1)
                *(float4*)(out + (size_t)sVox[v] * (GCH + HID) + GCH + 4 * tx) = h4;
        }
    }

    __syncthreads();
    for (int idx = tid; idx < MB * GCH; idx += NTHREADS) {
        int v = idx >> 6, g = idx & 63;
        out[(size_t)sVox[v] * (GCH + HID) + g] = sMax[idx];
    }
}

extern "C" void kernel_launch(void* const* d_in, const int* in_sizes, int n_in,
                              void* d_out, int out_size) {
    const float* inputs = (const float*)d_in[0];
    const int*   vnp    = (const int*)  d_in[1];
    // d_in[2] = mask (unused)
    const float* conv_w = (const float*)d_in[3];
    const float* bn_g   = (const float*)d_in[4];
    const float* bn_b   = (const float*)d_in[5];
    const float* bn_m   = (const float*)d_in[6];
    const float* bn_v   = (const float*)d_in[7];
    const float* wih0   = (const float*)d_in[8];
    const float* whh0   = (const float*)d_in[9];
    const float* bih0   = (const float*)d_in[10];
    const float* bhh0   = (const float*)d_in[11];
    const float* wih1   = (const float*)d_in[12];
    const float* whh1   = (const float*)d_in[13];
    const float* bih1   = (const float*)d_in[14];
    const float* bhh1   = (const float*)d_in[15];
    float* out = (float*)d_out;

    const int smem_bytes = (KT * H3 + MB * STR + MB * GCH + MB * CIN
                            + GCH * CIN + GCH + 4 * H3) * (int)sizeof(float)
                           + 2 * MB * (int)sizeof(int);
    cudaFuncSetAttribute(pfn_kernel, cudaFuncAttributeMaxDynamicSharedMemorySize, smem_bytes);

    zero_hist<<<1, 32>>>();
    hist_kernel<<<160, 256>>>(vnp);
    scan_kernel<<<1, 32>>>();
    binorder_kernel<<<32, 256>>>(vnp);
    prep_weights<<<336, 512>>>(wih0, whh0, wih1, whh1);
    pfn_kernel<<<NBLOCKS, NTHREADS, smem_bytes>>>(inputs, vnp, conv_w, bn_g, bn_b, bn_m, bn_v,
                                                  bih0, bhh0, bih1, bhh1, out);
}

// round 4
// speedup vs baseline: 3.2072x; 1.7346x over previous
#include <cuda_runtime.h>
#include <math.h>
#include <stdint.h>

// Shapes (fixed)
#define NVOX 40000
#define PPTS 32
#define CIN  10
#define GCH  64
#define HID  128
#define H3   384
#define MB   64
#define NTHREADS 256
#define NBLOCKS (NVOX / MB)     // 625
#define KT   32                 // K rows per weight tile
#define STR  320                // sA row: [x(64) | h1(128) | h2(128)]

// Stacked transposed weights WT[k][gate_col]:
// rows [0,64) Wih0^T, [64,192) Whh0^T, [192,320) Wih1^T, [320,448) Whh1^T
#define WT_ROWS 448
__device__ float g_WT[WT_ROWS * H3];
__device__ int   g_perm[NVOX];
__device__ int   g_hist[32];
__device__ int   g_off[33];
__device__ int   g_cursor[32];

__global__ void prep_weights(const float* __restrict__ wih0, const float* __restrict__ whh0,
                             const float* __restrict__ wih1, const float* __restrict__ whh1) {
    int idx = blockIdx.x * blockDim.x + threadIdx.x;
    const int total = WT_ROWS * H3;
    for (; idx < total; idx += gridDim.x * blockDim.x) {
        int row = idx / H3;
        int j   = idx - row * H3;
        float v;
        if (row < 64)       v = wih0[j * 64  + row];
        else if (row < 192) v = whh0[j * 128 + (row - 64)];
        else if (row < 320) v = wih1[j * 128 + (row - 192)];
        else                v = whh1[j * 128 + (row - 320)];
        g_WT[idx] = v;
    }
}

// ---- length binning (order within a bin unimportant: per-voxel outputs are independent) ----
__global__ void zero_hist() {
    if (threadIdx.x < 32) { g_hist[threadIdx.x] = 0; g_cursor[threadIdx.x] = 0; }
}
__global__ void hist_kernel(const int* __restrict__ vnp) {
    int i = blockIdx.x * blockDim.x + threadIdx.x;
    for (; i < NVOX; i += gridDim.x * blockDim.x)
        atomicAdd(&g_hist[vnp[i] - 1], 1);
}
__global__ void scan_kernel() {
    if (threadIdx.x == 0) {
        int acc = 0; g_off[0] = 0;
        for (int b = 0; b < 32; ++b) { acc += g_hist[b]; g_off[b + 1] = acc; }
    }
}
__global__ void sortblocks(const int* __restrict__ vnp) {
    __shared__ int cnt[32];
    __shared__ int sbase[32];
    const int tid = threadIdx.x;
    if (tid < 32) cnt[tid] = 0;
    __syncthreads();
    int i = blockIdx.x * 256 + tid;
    int len = -1, myrank = 0;
    if (i < NVOX) { len = vnp[i] - 1; myrank = atomicAdd(&cnt[len], 1); }
    __syncthreads();
    if (tid < 32 && cnt[tid] > 0) sbase[tid] = atomicAdd(&g_cursor[tid], cnt[tid]);
    __syncthreads();
    if (i < NVOX) g_perm[g_off[len] + sbase[len] + myrank] = i;
}

// ---- f32x2 helpers ----
__device__ __forceinline__ unsigned long long pack2(float lo, float hi) {
    unsigned long long r;
    asm("mov.b64 %0, {%1, %2};" : "=l"(r) : "f"(lo), "f"(hi));
    return r;
}
__device__ __forceinline__ void unpack2(unsigned long long v, float& lo, float& hi) {
    asm("mov.b64 {%0, %1}, %2;" : "=f"(lo), "=f"(hi) : "l"(v));
}
__device__ __forceinline__ void ffma2(unsigned long long& d, unsigned long long a, unsigned long long b) {
    asm("fma.rn.f32x2 %0, %1, %2, %0;" : "+l"(d) : "l"(a), "l"(b));
}
__device__ __forceinline__ float sigmoidf_(float x) { return 1.0f / (1.0f + expf(-x)); }

// cp.async one KT x 384 weight tile (49152 B = 3072 x 16B, 12 per thread)
__device__ __forceinline__ void cp_tile(uint32_t dst_s, const float* __restrict__ src, int tid) {
    const char* s = (const char*)src;
    #pragma unroll
    for (int r = 0; r < 12; ++r) {
        int idx = tid + r * NTHREADS;
        asm volatile("cp.async.cg.shared.global [%0], [%1], 16;\n"
                     :: "r"(dst_s + idx * 16), "l"(s + (size_t)idx * 16) : "memory");
    }
    asm volatile("cp.async.commit_group;\n" ::: "memory");
}

// One tile of the GEMM: A[v][k0..k0+31] x W[k][cols] -> f32x2 accumulators.
// Thread (tx,ty): voxels ty*8..ty*8+7, per-gate cols 4tx..4tx+3 (as 2 f32x2 pairs).
__device__ __forceinline__ void tile_compute(
    const float* __restrict__ buf, const float* __restrict__ sA0, int k0, int tx, int ty,
    unsigned long long (&aR)[8][2], unsigned long long (&aZ)[8][2], unsigned long long (&aN)[8][2])
{
    #pragma unroll 1
    for (int kk4 = 0; kk4 < KT / 4; ++kk4) {
        float4 a4[8];
        #pragma unroll
        for (int i = 0; i < 8; ++i)
            a4[i] = *(const float4*)(sA0 + (ty * 8 + i) * STR + k0 + kk4 * 4);
        #pragma unroll
        for (int j = 0; j < 4; ++j) {
            const float* wrow = buf + (kk4 * 4 + j) * H3 + 4 * tx;
            ulonglong2 wr = *(const ulonglong2*)(wrow);
            ulonglong2 wz = *(const ulonglong2*)(wrow + HID);
            ulonglong2 wn = *(const ulonglong2*)(wrow + 2 * HID);
            #pragma unroll
            for (int i = 0; i < 8; ++i) {
                float a = (j == 0) ? a4[i].x : (j == 1) ? a4[i].y
                        : (j == 2) ? a4[i].z : a4[i].w;
                unsigned long long a2 = pack2(a, a);
                ffma2(aR[i][0], a2, wr.x); ffma2(aR[i][1], a2, wr.y);
                ffma2(aZ[i][0], a2, wz.x); ffma2(aZ[i][1], a2, wz.y);
                ffma2(aN[i][0], a2, wn.x); ffma2(aN[i][1], a2, wn.y);
            }
        }
    }
}

// Double-buffered GEMM segment over WT rows [rowBase, rowBase+SEGK).
template<int SEGK>
__device__ __forceinline__ void gemm_seg(
    int rowBase, const float* __restrict__ sA0,
    const float* sW0, const float* sW1, uint32_t sW0a, uint32_t sW1a,
    int tid, int tx, int ty,
    unsigned long long (&aR)[8][2], unsigned long long (&aZ)[8][2], unsigned long long (&aN)[8][2])
{
    const int NT = SEGK / KT;     // 2 or 4 (even: buffer parity safe across calls)
    cp_tile(sW0a, g_WT + (size_t)rowBase * H3, tid);
    #pragma unroll 1
    for (int tile = 0; tile < NT; ++tile) {
        asm volatile("cp.async.wait_group 0;\n" ::: "memory");
        __syncthreads();
        if (tile + 1 < NT)
            cp_tile((tile & 1) ? sW0a : sW1a, g_WT + (size_t)(rowBase + (tile + 1) * KT) * H3, tid);
        tile_compute((tile & 1) ? sW1 : sW0, sA0, tile * KT, tx, ty, aR, aZ, aN);
    }
}

__global__ void __launch_bounds__(NTHREADS)
pfn_kernel(const float* __restrict__ inputs, const int* __restrict__ vnp,
           const float* __restrict__ conv_w,
           const float* __restrict__ bn_gamma, const float* __restrict__ bn_beta,
           const float* __restrict__ bn_mean,  const float* __restrict__ bn_var,
           const float* __restrict__ b_ih0, const float* __restrict__ b_hh0,
           const float* __restrict__ b_ih1, const float* __restrict__ b_hh1,
           float* __restrict__ out)
{
    extern __shared__ float sm[];
    float* sW0  = sm;                     // 12288
    float* sW1  = sW0 + KT * H3;          // 12288
    float* sA   = sW1 + KT * H3;          // 64*320
    float* sMax = sA  + MB * STR;         // 64*64
    float* sIn  = sMax + MB * GCH;        // 640
    float* sCw  = sIn  + MB * CIN;        // 640
    float* sCb  = sCw  + GCH * CIN;       // 64
    float* sB0i = sCb  + GCH;             // 4 x 384
    float* sB0h = sB0i + H3;
    float* sB1i = sB0h + H3;
    float* sB1h = sB1i + H3;
    int*   sLen = (int*)(sB1h + H3);      // 64
    int*   sVox = sLen + MB;              // 64

    const int tid = threadIdx.x;
    const int tx = tid & 31, ty = tid >> 5;
    // LPT: highest block id in the sorted permutation = longest voxels; give them to
    // the first-launched CTAs so the tail wave is short.
    const int pbase = (NBLOCKS - 1 - (int)blockIdx.x) * MB;

    const uint32_t sW0a = (uint32_t)__cvta_generic_to_shared(sW0);
    const uint32_t sW1a = (uint32_t)__cvta_generic_to_shared(sW1);

    // ---- one-time setup ----
    for (int idx = tid; idx < MB * STR; idx += NTHREADS) sA[idx] = 0.f;
    for (int idx = tid; idx < MB * GCH; idx += NTHREADS) sMax[idx] = 0.f;
    for (int idx = tid; idx < GCH * CIN; idx += NTHREADS) {
        int g = idx / CIN;
        float sc = bn_gamma[g] * rsqrtf(bn_var[g] + 1e-5f);
        sCw[idx] = conv_w[idx] * sc;
    }
    for (int idx = tid; idx < GCH; idx += NTHREADS) {
        float sc = bn_gamma[idx] * rsqrtf(bn_var[idx] + 1e-5f);
        sCb[idx] = bn_beta[idx] - bn_mean[idx] * sc;
    }
    for (int idx = tid; idx < H3; idx += NTHREADS) {
        sB0i[idx] = b_ih0[idx]; sB0h[idx] = b_hh0[idx];
        sB1i[idx] = b_ih1[idx]; sB1h[idx] = b_hh1[idx];
    }
    for (int idx = tid; idx < MB; idx += NTHREADS) {
        int vox = g_perm[pbase + idx];
        sVox[idx] = vox;
        sLen[idx] = vnp[vox];
    }
    __syncthreads();

    int tmax = 0;
    for (int v = 0; v < MB; ++v) tmax = max(tmax, sLen[v]);

    // ---- prepass: conv+BN+ReLU running max over all 32 points ----
    for (int t = 0; t < PPTS; ++t) {
        for (int idx = tid; idx < MB * CIN; idx += NTHREADS) {
            int v = idx / CIN, c = idx - v * CIN;
            sIn[idx] = inputs[((size_t)sVox[v] * PPTS + t) * CIN + c];
        }
        __syncthreads();
        for (int idx = tid; idx < MB * GCH; idx += NTHREADS) {
            int v = idx >> 6, g = idx & 63;
            float s = sCb[g];
            const float* pin = sIn + v * CIN;
            const float* pw  = sCw + g * CIN;
            #pragma unroll
            for (int c = 0; c < CIN; ++c) s = fmaf(pin[c], pw[c], s);
            sMax[idx] = fmaxf(sMax[idx], fmaxf(s, 0.f));
        }
        __syncthreads();
    }

    unsigned long long aR[8][2], aZ[8][2], aXN[8][2], aHN[8][2];

    for (int t = 0; t < tmax; ++t) {
        for (int idx = tid; idx < MB * CIN; idx += NTHREADS) {
            int v = idx / CIN, c = idx - v * CIN;
            sIn[idx] = inputs[((size_t)sVox[v] * PPTS + t) * CIN + c];
        }
        __syncthreads();
        for (int idx = tid; idx < MB * GCH; idx += NTHREADS) {
            int v = idx >> 6, g = idx & 63;
            float s = sCb[g];
            const float* pin = sIn + v * CIN;
            const float* pw  = sCw + g * CIN;
            #pragma unroll
            for (int c = 0; c < CIN; ++c) s = fmaf(pin[c], pw[c], s);
            sA[v * STR + g] = fmaxf(s, 0.f);     // x segment
        }
        // (gemm_seg tile 0 does wait+sync before compute: sA visible)

        // ======== layer 0 ========
        {
            int gc = 4 * tx;
            #pragma unroll
            for (int p = 0; p < 2; ++p) {
                unsigned long long br  = pack2(sB0i[gc+2*p]   + sB0h[gc+2*p],   sB0i[gc+2*p+1]   + sB0h[gc+2*p+1]);
                unsigned long long bz  = pack2(sB0i[128+gc+2*p] + sB0h[128+gc+2*p], sB0i[128+gc+2*p+1] + sB0h[128+gc+2*p+1]);
                unsigned long long bxn = pack2(sB0i[256+gc+2*p], sB0i[256+gc+2*p+1]);
                unsigned long long bhn = pack2(sB0h[256+gc+2*p], sB0h[256+gc+2*p+1]);
                #pragma unroll
                for (int i = 0; i < 8; ++i) { aR[i][p] = br; aZ[i][p] = bz; aXN[i][p] = bxn; aHN[i][p] = bhn; }
            }
        }
        gemm_seg<GCH>(0,  sA + 0,  sW0, sW1, sW0a, sW1a, tid, tx, ty, aR, aZ, aXN);
        gemm_seg<HID>(64, sA + 64, sW0, sW1, sW0a, sW1a, tid, tx, ty, aR, aZ, aHN);
        #pragma unroll
        for (int i = 0; i < 8; ++i) {
            int v = ty * 8 + i;
            float4 hp = *(const float4*)(sA + v * STR + 64 + 4 * tx);
            float rr[4], zz[4], xn[4], hn[4];
            unpack2(aR[i][0],  rr[0], rr[1]); unpack2(aR[i][1],  rr[2], rr[3]);
            unpack2(aZ[i][0],  zz[0], zz[1]); unpack2(aZ[i][1],  zz[2], zz[3]);
            unpack2(aXN[i][0], xn[0], xn[1]); unpack2(aXN[i][1], xn[2], xn[3]);
            unpack2(aHN[i][0], hn[0], hn[1]); unpack2(aHN[i][1], hn[2], hn[3]);
            float hv[4] = {hp.x, hp.y, hp.z, hp.w};
            #pragma unroll
            for (int j = 0; j < 4; ++j) {
                float r = sigmoidf_(rr[j]);
                float z = sigmoidf_(zz[j]);
                float n = tanhf(fmaf(r, hn[j], xn[j]));
                hv[j] = (1.f - z) * n + z * hv[j];
            }
            aR[i][0] = pack2(hv[0], hv[1]);   // h1_new kept in regs
            aR[i][1] = pack2(hv[2], hv[3]);
        }
        __syncthreads();                      // all reads of old h1 done
        #pragma unroll
        for (int i = 0; i < 8; ++i) {
            int v = ty * 8 + i;
            float a, b, c, d;
            unpack2(aR[i][0], a, b); unpack2(aR[i][1], c, d);
            *(float4*)(sA + v * STR + 64 + 4 * tx) = make_float4(a, b, c, d);
        }

        // ======== layer 1 ========
        {
            int gc = 4 * tx;
            #pragma unroll
            for (int p = 0; p < 2; ++p) {
                unsigned long long br  = pack2(sB1i[gc+2*p]   + sB1h[gc+2*p],   sB1i[gc+2*p+1]   + sB1h[gc+2*p+1]);
                unsigned long long bz  = pack2(sB1i[128+gc+2*p] + sB1h[128+gc+2*p], sB1i[128+gc+2*p+1] + sB1h[128+gc+2*p+1]);
                unsigned long long bxn = pack2(sB1i[256+gc+2*p], sB1i[256+gc+2*p+1]);
                unsigned long long bhn = pack2(sB1h[256+gc+2*p], sB1h[256+gc+2*p+1]);
                #pragma unroll
                for (int i = 0; i < 8; ++i) { aR[i][p] = br; aZ[i][p] = bz; aXN[i][p] = bxn; aHN[i][p] = bhn; }
            }
        }
        gemm_seg<HID>(192, sA + 64,  sW0, sW1, sW0a, sW1a, tid, tx, ty, aR, aZ, aXN);
        gemm_seg<HID>(320, sA + 192, sW0, sW1, sW0a, sW1a, tid, tx, ty, aR, aZ, aHN);
        #pragma unroll
        for (int i = 0; i < 8; ++i) {
            int v = ty * 8 + i;
            float4 hp = *(const float4*)(sA + v * STR + 192 + 4 * tx);
            float rr[4], zz[4], xn[4], hn[4];
            unpack2(aR[i][0],  rr[0], rr[1]); unpack2(aR[i][1],  rr[2], rr[3]);
            unpack2(aZ[i][0],  zz[0], zz[1]); unpack2(aZ[i][1],  zz[2], zz[3]);
            unpack2(aXN[i][0], xn[0], xn[1]); unpack2(aXN[i][1], xn[2], xn[3]);
            unpack2(aHN[i][0], hn[0], hn[1]); unpack2(aHN[i][1], hn[2], hn[3]);
            float hv[4] = {hp.x, hp.y, hp.z, hp.w};
            #pragma unroll
            for (int j = 0; j < 4; ++j) {
                float r = sigmoidf_(rr[j]);
                float z = sigmoidf_(zz[j]);
                float n = tanhf(fmaf(r, hn[j], xn[j]));
                hv[j] = (1.f - z) * n + z * hv[j];
            }
            aR[i][0] = pack2(hv[0], hv[1]);
            aR[i][1] = pack2(hv[2], hv[3]);
        }
        __syncthreads();                      // all reads of old h2 done
        #pragma unroll
        for (int i = 0; i < 8; ++i) {
            int v = ty * 8 + i;
            float a, b, c, d;
            unpack2(aR[i][0], a, b); unpack2(aR[i][1], c, d);
            float4 h4 = make_float4(a, b, c, d);
            *(float4*)(sA + v * STR + 192 + 4 * tx) = h4;
            if (t == sLen[v] - 1)
                *(float4*)(out + (size_t)sVox[v] * (GCH + HID) + GCH + 4 * tx) = h4;
        }
    }

    __syncthreads();
    for (int idx = tid; idx < MB * GCH; idx += NTHREADS) {
        int v = idx >> 6, g = idx & 63;
        out[(size_t)sVox[v] * (GCH + HID) + g] = sMax[idx];
    }
}

extern "C" void kernel_launch(void* const* d_in, const int* in_sizes, int n_in,
                              void* d_out, int out_size) {
    const float* inputs = (const float*)d_in[0];
    const int*   vnp    = (const int*)  d_in[1];
    // d_in[2] = mask (unused)
    const float* conv_w = (const float*)d_in[3];
    const float* bn_g   = (const float*)d_in[4];
    const float* bn_b   = (const float*)d_in[5];
    const float* bn_m   = (const float*)d_in[6];
    const float* bn_v   = (const float*)d_in[7];
    const float* wih0   = (const float*)d_in[8];
    const float* whh0   = (const float*)d_in[9];
    const float* bih0   = (const float*)d_in[10];
    const float* bhh0   = (const float*)d_in[11];
    const float* wih1   = (const float*)d_in[12];
    const float* whh1   = (const float*)d_in[13];
    const float* bih1   = (const float*)d_in[14];
    const float* bhh1   = (const float*)d_in[15];
    float* out = (float*)d_out;

    const int smem_bytes = (2 * KT * H3 + MB * STR + MB * GCH + MB * CIN
                            + GCH * CIN + GCH + 4 * H3) * (int)sizeof(float)
                           + 2 * MB * (int)sizeof(int);
    cudaFuncSetAttribute(pfn_kernel, cudaFuncAttributeMaxDynamicSharedMemorySize, smem_bytes);

    zero_hist<<<1, 32>>>();
    hist_kernel<<<160, 256>>>(vnp);
    scan_kernel<<<1, 32>>>();
    sortblocks<<<(NVOX + 255) / 256, 256>>>(vnp);
    prep_weights<<<336, 512>>>(wih0, whh0, wih1, whh1);
    pfn_kernel<<<NBLOCKS, NTHREADS, smem_bytes>>>(inputs, vnp, conv_w, bn_g, bn_b, bn_m, bn_v,
                                                  bih0, bhh0, bih1, bhh1, out);
}

// round 5
// speedup vs baseline: 3.5872x; 1.1185x over previous
#include <cuda_runtime.h>
#include <math.h>
#include <stdint.h>

// Shapes (fixed)
#define NVOX 40000
#define PPTS 32
#define CIN  10
#define GCH  64
#define HID  128
#define H3   384
#define MB   64
#define NTHREADS 256
#define NBLOCKS (NVOX / MB)     // 625
#define KT   32                 // K rows per weight tile
#define STR  320                // sA row: [x(64) | h1(128) | h2(128)]

// Stacked transposed weights WT[k][gate_col]:
// rows [0,64) Wih0^T, [64,192) Whh0^T, [192,320) Wih1^T, [320,448) Whh1^T
#define WT_ROWS 448
__device__ float g_WT[WT_ROWS * H3];
__device__ int   g_perm[NVOX];
__device__ int   g_hist[32];
__device__ int   g_off[33];
__device__ int   g_cursor[32];

__global__ void prep_weights(const float* __restrict__ wih0, const float* __restrict__ whh0,
                             const float* __restrict__ wih1, const float* __restrict__ whh1) {
    int idx = blockIdx.x * blockDim.x + threadIdx.x;
    const int total = WT_ROWS * H3;
    for (; idx < total; idx += gridDim.x * blockDim.x) {
        int row = idx / H3;
        int j   = idx - row * H3;
        float v;
        if (row < 64)       v = wih0[j * 64  + row];
        else if (row < 192) v = whh0[j * 128 + (row - 64)];
        else if (row < 320) v = wih1[j * 128 + (row - 192)];
        else                v = whh1[j * 128 + (row - 320)];
        g_WT[idx] = v;
    }
}

// ---- length binning (order within a bin unimportant: per-voxel outputs independent) ----
__global__ void zero_hist() {
    if (threadIdx.x < 32) { g_hist[threadIdx.x] = 0; g_cursor[threadIdx.x] = 0; }
}
__global__ void hist_kernel(const int* __restrict__ vnp) {
    int i = blockIdx.x * blockDim.x + threadIdx.x;
    for (; i < NVOX; i += gridDim.x * blockDim.x)
        atomicAdd(&g_hist[vnp[i] - 1], 1);
}
__global__ void scan_kernel() {
    if (threadIdx.x == 0) {
        int acc = 0; g_off[0] = 0;
        for (int b = 0; b < 32; ++b) { acc += g_hist[b]; g_off[b + 1] = acc; }
    }
}
__global__ void sortblocks(const int* __restrict__ vnp) {
    __shared__ int cnt[32];
    __shared__ int sbase[32];
    const int tid = threadIdx.x;
    if (tid < 32) cnt[tid] = 0;
    __syncthreads();
    int i = blockIdx.x * 256 + tid;
    int len = -1, myrank = 0;
    if (i < NVOX) { len = vnp[i] - 1; myrank = atomicAdd(&cnt[len], 1); }
    __syncthreads();
    if (tid < 32 && cnt[tid] > 0) sbase[tid] = atomicAdd(&g_cursor[tid], cnt[tid]);
    __syncthreads();
    if (i < NVOX) g_perm[g_off[len] + sbase[len] + myrank] = i;
}

// ---- f32x2 helpers ----
__device__ __forceinline__ unsigned long long pack2(float lo, float hi) {
    unsigned long long r;
    asm("mov.b64 %0, {%1, %2};" : "=l"(r) : "f"(lo), "f"(hi));
    return r;
}
__device__ __forceinline__ void unpack2(unsigned long long v, float& lo, float& hi) {
    asm("mov.b64 {%0, %1}, %2;" : "=f"(lo), "=f"(hi) : "l"(v));
}
__device__ __forceinline__ void ffma2(unsigned long long& d, unsigned long long a, unsigned long long b) {
    asm("fma.rn.f32x2 %0, %1, %2, %0;" : "+l"(d) : "l"(a), "l"(b));
}
// Fast gates via MUFU paths (~2 ulp): saturate correctly at both tails.
__device__ __forceinline__ float fsig(float x)  { return __fdividef(1.f, 1.f + __expf(-x)); }
__device__ __forceinline__ float ftanh_(float x){ return 1.f - __fdividef(2.f, __expf(2.f * x) + 1.f); }

// cp.async one KT x 384 weight tile (49152 B = 3072 x 16B, 12 per thread)
__device__ __forceinline__ void cp_tile(uint32_t dst_s, const float* __restrict__ src, int tid) {
    const char* s = (const char*)src;
    #pragma unroll
    for (int r = 0; r < 12; ++r) {
        int idx = tid + r * NTHREADS;
        asm volatile("cp.async.cg.shared.global [%0], [%1], 16;\n"
                     :: "r"(dst_s + idx * 16), "l"(s + (size_t)idx * 16) : "memory");
    }
    asm volatile("cp.async.commit_group;\n" ::: "memory");
}

// One KT-tile GEMM: A[v][.] x W[k][cols] -> f32x2 accumulators.
// Software-pipelined: weight row kk+1 prefetched during kk's FFMA2 block.
// (kk=31 prefetch over-reads one row into the adjacent smem region: allocated, unused.)
__device__ __forceinline__ void tile_compute(
    const float* __restrict__ buf, const float* __restrict__ sA0, int tx, int ty,
    unsigned long long (&aR)[8][2], unsigned long long (&aZ)[8][2], unsigned long long (&aN)[8][2])
{
    const float* wcol = buf + 4 * tx;
    ulonglong2 wr = *(const ulonglong2*)(wcol);
    ulonglong2 wz = *(const ulonglong2*)(wcol + HID);
    ulonglong2 wn = *(const ulonglong2*)(wcol + 2 * HID);
    #pragma unroll 2
    for (int kk4 = 0; kk4 < KT / 4; ++kk4) {
        float4 a4[8];
        #pragma unroll
        for (int i = 0; i < 8; ++i)
            a4[i] = *(const float4*)(sA0 + (ty * 8 + i) * STR + kk4 * 4);
        #pragma unroll
        for (int j = 0; j < 4; ++j) {
            const float* nrow = wcol + (kk4 * 4 + j + 1) * H3;
            ulonglong2 nr = *(const ulonglong2*)(nrow);
            ulonglong2 nz = *(const ulonglong2*)(nrow + HID);
            ulonglong2 nn = *(const ulonglong2*)(nrow + 2 * HID);
            #pragma unroll
            for (int i = 0; i < 8; ++i) {
                float a = (j == 0) ? a4[i].x : (j == 1) ? a4[i].y
                        : (j == 2) ? a4[i].z : a4[i].w;
                unsigned long long a2 = pack2(a, a);
                ffma2(aR[i][0], a2, wr.x); ffma2(aR[i][1], a2, wr.y);
                ffma2(aZ[i][0], a2, wz.x); ffma2(aZ[i][1], a2, wz.y);
                ffma2(aN[i][0], a2, wn.x); ffma2(aN[i][1], a2, wn.y);
            }
            wr = nr; wz = nz; wn = nn;
        }
    }
}

// Double-buffered GEMM segment over WT rows [rowBase, rowBase+SEGK).
template<int SEGK>
__device__ __forceinline__ void gemm_seg(
    int rowBase, const float* __restrict__ sA0,
    const float* sW0, const float* sW1, uint32_t sW0a, uint32_t sW1a,
    int tid, int tx, int ty,
    unsigned long long (&aR)[8][2], unsigned long long (&aZ)[8][2], unsigned long long (&aN)[8][2])
{
    const int NT = SEGK / KT;     // even: buffer parity safe across calls
    cp_tile(sW0a, g_WT + (size_t)rowBase * H3, tid);
    #pragma unroll 1
    for (int tile = 0; tile < NT; ++tile) {
        asm volatile("cp.async.wait_group 0;\n" ::: "memory");
        __syncthreads();
        if (tile + 1 < NT)
            cp_tile((tile & 1) ? sW0a : sW1a, g_WT + (size_t)(rowBase + (tile + 1) * KT) * H3, tid);
        tile_compute((tile & 1) ? sW1 : sW0, sA0 + tile * KT, tx, ty, aR, aZ, aN);
    }
}

__global__ void __launch_bounds__(NTHREADS)
pfn_kernel(const float* __restrict__ inputs, const int* __restrict__ vnp,
           const float* __restrict__ conv_w,
           const float* __restrict__ bn_gamma, const float* __restrict__ bn_beta,
           const float* __restrict__ bn_mean,  const float* __restrict__ bn_var,
           const float* __restrict__ b_ih0, const float* __restrict__ b_hh0,
           const float* __restrict__ b_ih1, const float* __restrict__ b_hh1,
           float* __restrict__ out)
{
    extern __shared__ float sm[];
    float* sW0  = sm;                     // 12288
    float* sW1  = sW0 + KT * H3;          // 12288
    float* sA   = sW1 + KT * H3;          // 64*320
    float* sMax = sA  + MB * STR;         // 64*64
    float* sIn  = sMax + MB * GCH;        // 640
    float* sCw  = sIn  + MB * CIN;        // 640
    float* sCb  = sCw  + GCH * CIN;       // 64
    float* sB0i = sCb  + GCH;             // 4 x 384
    float* sB0h = sB0i + H3;
    float* sB1i = sB0h + H3;
    float* sB1h = sB1i + H3;
    int*   sLen = (int*)(sB1h + H3);      // 64
    int*   sVox = sLen + MB;              // 64

    const int tid = threadIdx.x;
    const int tx = tid & 31, ty = tid >> 5;
    // LPT: highest permutation index = longest voxels; first-launched CTAs take them.
    const int pbase = (NBLOCKS - 1 - (int)blockIdx.x) * MB;

    const uint32_t sW0a = (uint32_t)__cvta_generic_to_shared(sW0);
    const uint32_t sW1a = (uint32_t)__cvta_generic_to_shared(sW1);

    // ---- one-time setup ----
    for (int idx = tid; idx < MB * STR; idx += NTHREADS) sA[idx] = 0.f;
    for (int idx = tid; idx < MB * GCH; idx += NTHREADS) sMax[idx] = 0.f;
    for (int idx = tid; idx < GCH * CIN; idx += NTHREADS) {
        int g = idx / CIN;
        float sc = bn_gamma[g] * rsqrtf(bn_var[g] + 1e-5f);
        sCw[idx] = conv_w[idx] * sc;
    }
    for (int idx = tid; idx < GCH; idx += NTHREADS) {
        float sc = bn_gamma[idx] * rsqrtf(bn_var[idx] + 1e-5f);
        sCb[idx] = bn_beta[idx] - bn_mean[idx] * sc;
    }
    for (int idx = tid; idx < H3; idx += NTHREADS) {
        sB0i[idx] = b_ih0[idx]; sB0h[idx] = b_hh0[idx];
        sB1i[idx] = b_ih1[idx]; sB1h[idx] = b_hh1[idx];
    }
    for (int idx = tid; idx < MB; idx += NTHREADS) {
        int vox = g_perm[pbase + idx];
        sVox[idx] = vox;
        sLen[idx] = vnp[vox];
    }
    __syncthreads();

    int tmax = 0;
    for (int v = 0; v < MB; ++v) tmax = max(tmax, sLen[v]);

    unsigned long long aR[8][2], aZ[8][2], aXN[8][2], aHN[8][2];

    // ---- GRU loop (conv + max fused here for t < tmax) ----
    for (int t = 0; t < tmax; ++t) {
        for (int idx = tid; idx < MB * CIN; idx += NTHREADS) {
            int v = idx / CIN, c = idx - v * CIN;
            sIn[idx] = inputs[((size_t)sVox[v] * PPTS + t) * CIN + c];
        }
        __syncthreads();
        for (int idx = tid; idx < MB * GCH; idx += NTHREADS) {
            int v = idx >> 6, g = idx & 63;
            float s = sCb[g];
            const float* pin = sIn + v * CIN;
            const float* pw  = sCw + g * CIN;
            #pragma unroll
            for (int c = 0; c < CIN; ++c) s = fmaf(pin[c], pw[c], s);
            s = fmaxf(s, 0.f);
            sA[v * STR + g] = s;                 // x segment
            sMax[idx] = fmaxf(sMax[idx], s);     // running max (same-thread ownership)
        }
        // (gemm_seg tile 0 does wait+sync before compute: sA visible)

        // ======== layer 0 ========
        {
            int gc = 4 * tx;
            #pragma unroll
            for (int p = 0; p < 2; ++p) {
                unsigned long long br  = pack2(sB0i[gc+2*p]   + sB0h[gc+2*p],   sB0i[gc+2*p+1]   + sB0h[gc+2*p+1]);
                unsigned long long bz  = pack2(sB0i[128+gc+2*p] + sB0h[128+gc+2*p], sB0i[128+gc+2*p+1] + sB0h[128+gc+2*p+1]);
                unsigned long long bxn = pack2(sB0i[256+gc+2*p], sB0i[256+gc+2*p+1]);
                unsigned long long bhn = pack2(sB0h[256+gc+2*p], sB0h[256+gc+2*p+1]);
                #pragma unroll
                for (int i = 0; i < 8; ++i) { aR[i][p] = br; aZ[i][p] = bz; aXN[i][p] = bxn; aHN[i][p] = bhn; }
            }
        }
        gemm_seg<GCH>(0,  sA + 0,  sW0, sW1, sW0a, sW1a, tid, tx, ty, aR, aZ, aXN);
        gemm_seg<HID>(64, sA + 64, sW0, sW1, sW0a, sW1a, tid, tx, ty, aR, aZ, aHN);
        #pragma unroll
        for (int i = 0; i < 8; ++i) {
            int v = ty * 8 + i;
            float4 hp = *(const float4*)(sA + v * STR + 64 + 4 * tx);
            float rr[4], zz[4], xn[4], hn[4];
            unpack2(aR[i][0],  rr[0], rr[1]); unpack2(aR[i][1],  rr[2], rr[3]);
            unpack2(aZ[i][0],  zz[0], zz[1]); unpack2(aZ[i][1],  zz[2], zz[3]);
            unpack2(aXN[i][0], xn[0], xn[1]); unpack2(aXN[i][1], xn[2], xn[3]);
            unpack2(aHN[i][0], hn[0], hn[1]); unpack2(aHN[i][1], hn[2], hn[3]);
            float hv[4] = {hp.x, hp.y, hp.z, hp.w};
            #pragma unroll
            for (int j = 0; j < 4; ++j) {
                float r = fsig(rr[j]);
                float z = fsig(zz[j]);
                float n = ftanh_(fmaf(r, hn[j], xn[j]));
                hv[j] = (1.f - z) * n + z * hv[j];
            }
            aR[i][0] = pack2(hv[0], hv[1]);   // h1_new in regs
            aR[i][1] = pack2(hv[2], hv[3]);
        }
        __syncthreads();                      // all reads of old h1 done
        #pragma unroll
        for (int i = 0; i < 8; ++i) {
            int v = ty * 8 + i;
            float a, b, c, d;
            unpack2(aR[i][0], a, b); unpack2(aR[i][1], c, d);
            *(float4*)(sA + v * STR + 64 + 4 * tx) = make_float4(a, b, c, d);
        }

        // ======== layer 1 ========
        {
            int gc = 4 * tx;
            #pragma unroll
            for (int p = 0; p < 2; ++p) {
                unsigned long long br  = pack2(sB1i[gc+2*p]   + sB1h[gc+2*p],   sB1i[gc+2*p+1]   + sB1h[gc+2*p+1]);
                unsigned long long bz  = pack2(sB1i[128+gc+2*p] + sB1h[128+gc+2*p], sB1i[128+gc+2*p+1] + sB1h[128+gc+2*p+1]);
                unsigned long long bxn = pack2(sB1i[256+gc+2*p], sB1i[256+gc+2*p+1]);
                unsigned long long bhn = pack2(sB1h[256+gc+2*p], sB1h[256+gc+2*p+1]);
                #pragma unroll
                for (int i = 0; i < 8; ++i) { aR[i][p] = br; aZ[i][p] = bz; aXN[i][p] = bxn; aHN[i][p] = bhn; }
            }
        }
        gemm_seg<HID>(192, sA + 64,  sW0, sW1, sW0a, sW1a, tid, tx, ty, aR, aZ, aXN);
        gemm_seg<HID>(320, sA + 192, sW0, sW1, sW0a, sW1a, tid, tx, ty, aR, aZ, aHN);
        #pragma unroll
        for (int i = 0; i < 8; ++i) {
            int v = ty * 8 + i;
            float4 hp = *(const float4*)(sA + v * STR + 192 + 4 * tx);
            float rr[4], zz[4], xn[4], hn[4];
            unpack2(aR[i][0],  rr[0], rr[1]); unpack2(aR[i][1],  rr[2], rr[3]);
            unpack2(aZ[i][0],  zz[0], zz[1]); unpack2(aZ[i][1],  zz[2], zz[3]);
            unpack2(aXN[i][0], xn[0], xn[1]); unpack2(aXN[i][1], xn[2], xn[3]);
            unpack2(aHN[i][0], hn[0], hn[1]); unpack2(aHN[i][1], hn[2], hn[3]);
            float hv[4] = {hp.x, hp.y, hp.z, hp.w};
            #pragma unroll
            for (int j = 0; j < 4; ++j) {
                float r = fsig(rr[j]);
                float z = fsig(zz[j]);
                float n = ftanh_(fmaf(r, hn[j], xn[j]));
                hv[j] = (1.f - z) * n + z * hv[j];
            }
            aR[i][0] = pack2(hv[0], hv[1]);
            aR[i][1] = pack2(hv[2], hv[3]);
        }
        __syncthreads();                      // all reads of old h2 done
        #pragma unroll
        for (int i = 0; i < 8; ++i) {
            int v = ty * 8 + i;
            float a, b, c, d;
            unpack2(aR[i][0], a, b); unpack2(aR[i][1], c, d);
            float4 h4 = make_float4(a, b, c, d);
            *(float4*)(sA + v * STR + 192 + 4 * tx) = h4;
            if (t == sLen[v] - 1)
                *(float4*)(out + (size_t)sVox[v] * (GCH + HID) + GCH + 4 * tx) = h4;
        }
    }

    // ---- tail: conv+max only for t in [tmax, 32) ----
    for (int t = tmax; t < PPTS; ++t) {
        __syncthreads();
        for (int idx = tid; idx < MB * CIN; idx += NTHREADS) {
            int v = idx / CIN, c = idx - v * CIN;
            sIn[idx] = inputs[((size_t)sVox[v] * PPTS + t) * CIN + c];
        }
        __syncthreads();
        for (int idx = tid; idx < MB * GCH; idx += NTHREADS) {
            int v = idx >> 6, g = idx & 63;
            float s = sCb[g];
            const float* pin = sIn + v * CIN;
            const float* pw  = sCw + g * CIN;
            #pragma unroll
            for (int c = 0; c < CIN; ++c) s = fmaf(pin[c], pw[c], s);
            sMax[idx] = fmaxf(sMax[idx], fmaxf(s, 0.f));
        }
    }

    __syncthreads();
    for (int idx = tid; idx < MB * GCH; idx += NTHREADS) {
        int v = idx >> 6, g = idx & 63;
        out[(size_t)sVox[v] * (GCH + HID) + g] = sMax[idx];
    }
}

extern "C" void kernel_launch(void* const* d_in, const int* in_sizes, int n_in,
                              void* d_out, int out_size) {
    const float* inputs = (const float*)d_in[0];
    const int*   vnp    = (const int*)  d_in[1];
    // d_in[2] = mask (unused)
    const float* conv_w = (const float*)d_in[3];
    const float* bn_g   = (const float*)d_in[4];
    const float* bn_b   = (const float*)d_in[5];
    const float* bn_m   = (const float*)d_in[6];
    const float* bn_v   = (const float*)d_in[7];
    const float* wih0   = (const float*)d_in[8];
    const float* whh0   = (const float*)d_in[9];
    const float* bih0   = (const float*)d_in[10];
    const float* bhh0   = (const float*)d_in[11];
    const float* wih1   = (const float*)d_in[12];
    const float* whh1   = (const float*)d_in[13];
    const float* bih1   = (const float*)d_in[14];
    const float* bhh1   = (const float*)d_in[15];
    float* out = (float*)d_out;

    const int smem_bytes = (2 * KT * H3 + MB * STR + MB * GCH + MB * CIN
                            + GCH * CIN + GCH + 4 * H3) * (int)sizeof(float)
                           + 2 * MB * (int)sizeof(int);
    cudaFuncSetAttribute(pfn_kernel, cudaFuncAttributeMaxDynamicSharedMemorySize, smem_bytes);

    zero_hist<<<1, 32>>>();
    hist_kernel<<<160, 256>>>(vnp);
    scan_kernel<<<1, 32>>>();
    sortblocks<<<(NVOX + 255) / 256, 256>>>(vnp);
    prep_weights<<<336, 512>>>(wih0, whh0, wih1, whh1);
    pfn_kernel<<<NBLOCKS, NTHREADS, smem_bytes>>>(inputs, vnp, conv_w, bn_g, bn_b, bn_m, bn_v,
                                                  bih0, bhh0, bih1, bhh1, out);
}